// round 3
// baseline (speedup 1.0000x reference)
#include <cuda_runtime.h>

#define CH    128
#define NGRP  8
#define CPG   16
#define NBATCH 2
#define NSP   8192
#define EPSF  1e-5f

// ---- scratch (device globals; no allocations allowed) ----
__device__ float g_mean[NBATCH * NGRP];
__device__ float g_rstd[NBATCH * NGRP];
__device__ float g_q [NBATCH * NSP * CH];
__device__ float g_k [NBATCH * NSP * CH];
__device__ float g_v [NBATCH * NSP * CH];
__device__ float g_ao[NBATCH * NSP * CH];

// ================= Kernel 1: GroupNorm statistics =================
// One block per (batch, group). Group = 16 contiguous channels x 8192 voxels.
__global__ void gn_stats_kernel(const float* __restrict__ x) {
    const int bg = blockIdx.x;
    const int b = bg >> 3, g = bg & 7;
    const float* base = x + ((size_t)b * CH + g * CPG) * NSP;
    const int total = CPG * NSP;           // 131072, contiguous
    const int tid = threadIdx.x;
    float s = 0.f, ss = 0.f;
    const float4* p4 = (const float4*)base;
    for (int i = tid; i < total / 4; i += 256) {
        float4 v = p4[i];
        s  += (v.x + v.y) + (v.z + v.w);
        ss += (v.x * v.x + v.y * v.y) + (v.z * v.z + v.w * v.w);
    }
    __shared__ float shs[256], shss[256];
    shs[tid] = s; shss[tid] = ss;
    __syncthreads();
    for (int o = 128; o > 0; o >>= 1) {
        if (tid < o) { shs[tid] += shs[tid + o]; shss[tid] += shss[tid + o]; }
        __syncthreads();
    }
    if (tid == 0) {
        float mean = shs[0] / (float)total;
        float var  = shss[0] / (float)total - mean * mean;
        g_mean[bg] = mean;
        g_rstd[bg] = rsqrtf(var + EPSF);
    }
}

// ================= Kernel 2: fused GroupNorm-apply + QKV GEMM =================
// out[b,n,o] = sum_c normalize(x[b,c,n]) * w_qkv[o,c] + b_qkv[o]
// M = B*N = 16384 (rows n), N = 384 (o), K = 128 (c). Writes q/k/v in [B,N,C].
__global__ __launch_bounds__(128) void qkv_gemm_kernel(
    const float* __restrict__ x, const float* __restrict__ gamma,
    const float* __restrict__ beta, const float* __restrict__ w,
    const float* __restrict__ bias)
{
    __shared__ float sA[32][65];
    __shared__ float sB[32][65];
    const int mblk = blockIdx.x;
    const int b  = mblk >> 7;
    const int n0 = (mblk & 127) << 6;
    const int o0 = blockIdx.y << 6;
    const int tid = threadIdx.x;
    const int ty = tid >> 3, tx = tid & 7;
    const int mr = ty << 2;   // 4 rows
    const int oc = tx << 3;   // 8 cols
    float acc[4][8];
#pragma unroll
    for (int i = 0; i < 4; i++)
#pragma unroll
        for (int j = 0; j < 8; j++) acc[i][j] = 0.f;

    for (int k0 = 0; k0 < CH; k0 += 32) {
        // A tile: x is [B,C,N] so rows (c) are contiguous in n -> coalesced.
#pragma unroll
        for (int i = tid; i < 32 * 64; i += 128) {
            int kk = i >> 6, m = i & 63;
            int c = k0 + kk;
            int bg = (b << 3) + (c >> 4);
            float xv = x[((size_t)b * CH + c) * NSP + n0 + m];
            sA[kk][m] = (xv - g_mean[bg]) * g_rstd[bg] * gamma[c] + beta[c];
        }
        // B tile: w[o][c] -> sB[kk][o]
#pragma unroll
        for (int i = tid; i < 64 * 32; i += 128) {
            int o = i >> 5, kk = i & 31;
            sB[kk][o] = w[(size_t)(o0 + o) * CH + k0 + kk];
        }
        __syncthreads();
#pragma unroll
        for (int kk = 0; kk < 32; kk++) {
            float a[4], bb[8];
#pragma unroll
            for (int i = 0; i < 4; i++) a[i] = sA[kk][mr + i];
#pragma unroll
            for (int j = 0; j < 8; j++) bb[j] = sB[kk][oc + j];
#pragma unroll
            for (int i = 0; i < 4; i++)
#pragma unroll
                for (int j = 0; j < 8; j++) acc[i][j] += a[i] * bb[j];
        }
        __syncthreads();
    }
    const int og = o0 + oc;                       // whole block is in one of q/k/v
    float* dst = (og < CH) ? g_q : ((og < 2 * CH) ? g_k : g_v);
    const int ob = og & (CH - 1);
#pragma unroll
    for (int i = 0; i < 4; i++) {
        size_t row = ((size_t)b * NSP + n0 + mr + i) * CH;
#pragma unroll
        for (int j = 0; j < 8; j++)
            dst[row + ob + j] = acc[i][j] + bias[og + j];
    }
}

// ================= Kernel 3: flash attention (fp32 SIMT) =================
// Block: 64 queries, loops over 128 key tiles of 64. 128 threads (16x8).
// smem: sQ/sK K-major XOR-swizzled [128][64], sV [64][128], sP j-major [64][65].
// Total 112.25 KB -> 2 CTAs/SM -> one full wave (256 blocks).
__global__ __launch_bounds__(128) void attn_kernel() {
    extern __shared__ float sm[];
    float* sQ = sm;              // 128*64
    float* sK = sm + 8192;       // 128*64
    float* sV = sm + 16384;      // 64*128
    float* sP = sm + 24576;      // 64*65   (sP[j][r])
    const int b  = blockIdx.y;
    const int n0 = blockIdx.x << 6;
    const int tid = threadIdx.x;
    const int ty = tid >> 3, tx = tid & 7;
    const int r0 = ty << 2;      // 4 query rows
    const int j0 = tx << 3;      // 8 score cols
    const int c0 = tx << 4;      // 16 output channels
    const float scale = 0.08838834764831845f;  // 1/sqrt(128)

    const size_t qbase = ((size_t)b * NSP + n0) * CH;
    for (int i = tid; i < 64 * CH; i += 128) {
        int m = i >> 7, c = i & 127;
        sQ[(c << 6) + (m ^ (c & 31))] = g_q[qbase + (size_t)m * CH + c] * scale;
    }

    float O[4][16];
#pragma unroll
    for (int i = 0; i < 4; i++)
#pragma unroll
        for (int j = 0; j < 16; j++) O[i][j] = 0.f;
    float mr[4], lr[4];
#pragma unroll
    for (int i = 0; i < 4; i++) { mr[i] = -3.4e38f; lr[i] = 0.f; }

    for (int t = 0; t < NSP / 64; t++) {
        __syncthreads();   // prev PV done reading sV/sP
        const size_t kb = ((size_t)b * NSP + (size_t)t * 64) * CH;
        for (int i = tid; i < 64 * CH; i += 128) {
            int j = i >> 7, c = i & 127;
            sK[(c << 6) + (j ^ (c & 31))] = g_k[kb + (size_t)j * CH + c];
            sV[(j << 7) + c]              = g_v[kb + (size_t)j * CH + c];
        }
        __syncthreads();

        // S = Qs @ K^T   (4x8 per thread)
        float S[4][8];
#pragma unroll
        for (int i = 0; i < 4; i++)
#pragma unroll
            for (int j = 0; j < 8; j++) S[i][j] = 0.f;
#pragma unroll 8
        for (int k = 0; k < CH; k++) {
            const float* qrow = sQ + (k << 6);
            const float* krow = sK + (k << 6);
            const int sw = k & 31;
            float qv[4], kv[8];
#pragma unroll
            for (int i = 0; i < 4; i++) qv[i] = qrow[(r0 + i) ^ sw];
#pragma unroll
            for (int j = 0; j < 8; j++) kv[j] = krow[(j0 + j) ^ sw];
#pragma unroll
            for (int i = 0; i < 4; i++)
#pragma unroll
                for (int j = 0; j < 8; j++) S[i][j] += qv[i] * kv[j];
        }

        // online softmax (row groups of 8 tx lanes)
#pragma unroll
        for (int i = 0; i < 4; i++) {
            float mx = S[i][0];
#pragma unroll
            for (int j = 1; j < 8; j++) mx = fmaxf(mx, S[i][j]);
            mx = fmaxf(mx, __shfl_xor_sync(0xffffffffu, mx, 1));
            mx = fmaxf(mx, __shfl_xor_sync(0xffffffffu, mx, 2));
            mx = fmaxf(mx, __shfl_xor_sync(0xffffffffu, mx, 4));
            float mnew  = fmaxf(mr[i], mx);
            float alpha = __expf(mr[i] - mnew);
            mr[i] = mnew;
            float ls = 0.f;
#pragma unroll
            for (int j = 0; j < 8; j++) {
                float p = __expf(S[i][j] - mnew);
                S[i][j] = p; ls += p;
            }
            ls += __shfl_xor_sync(0xffffffffu, ls, 1);
            ls += __shfl_xor_sync(0xffffffffu, ls, 2);
            ls += __shfl_xor_sync(0xffffffffu, ls, 4);
            lr[i] = lr[i] * alpha + ls;
#pragma unroll
            for (int cc = 0; cc < 16; cc++) O[i][cc] *= alpha;
#pragma unroll
            for (int j = 0; j < 8; j++) sP[(j0 + j) * 65 + r0 + i] = S[i][j];
        }
        __syncthreads();

        // O += P @ V   (4x16 per thread)
#pragma unroll 4
        for (int j = 0; j < 64; j++) {
            const float4* vr = (const float4*)(sV + (j << 7) + c0);
            float4 v0 = vr[0], v1 = vr[1], v2 = vr[2], v3 = vr[3];
#pragma unroll
            for (int i = 0; i < 4; i++) {
                float p = sP[j * 65 + r0 + i];
                O[i][0]  += p * v0.x; O[i][1]  += p * v0.y; O[i][2]  += p * v0.z; O[i][3]  += p * v0.w;
                O[i][4]  += p * v1.x; O[i][5]  += p * v1.y; O[i][6]  += p * v1.z; O[i][7]  += p * v1.w;
                O[i][8]  += p * v2.x; O[i][9]  += p * v2.y; O[i][10] += p * v2.z; O[i][11] += p * v2.w;
                O[i][12] += p * v3.x; O[i][13] += p * v3.y; O[i][14] += p * v3.z; O[i][15] += p * v3.w;
            }
        }
    }

    const size_t ob = ((size_t)b * NSP + n0) * CH;
#pragma unroll
    for (int i = 0; i < 4; i++) {
        float inv = 1.f / lr[i];
        float4* dst = (float4*)(g_ao + ob + (size_t)(r0 + i) * CH + c0);
#pragma unroll
        for (int q4 = 0; q4 < 4; q4++) {
            float4 w4;
            w4.x = O[i][q4 * 4 + 0] * inv;
            w4.y = O[i][q4 * 4 + 1] * inv;
            w4.z = O[i][q4 * 4 + 2] * inv;
            w4.w = O[i][q4 * 4 + 3] * inv;
            dst[q4] = w4;
        }
    }
}

// ================= Kernel 4: proj GEMM + bias + residual =================
// out[b,c,n] = x[b,c,n] + sum_c' ao[b,n,c'] * w_proj[c,c'] + b_proj[c]
__global__ __launch_bounds__(128) void proj_gemm_kernel(
    const float* __restrict__ x, const float* __restrict__ w,
    const float* __restrict__ bias, float* __restrict__ out)
{
    __shared__ float sA[32][65];
    __shared__ float sB[32][65];
    const int mblk = blockIdx.x;
    const int b  = mblk >> 7;
    const int n0 = (mblk & 127) << 6;
    const int o0 = blockIdx.y << 6;
    const int tid = threadIdx.x;
    const int ty = tid >> 3, tx = tid & 7;
    const int mr = ty << 2;
    const int oc = tx << 3;
    float acc[4][8];
#pragma unroll
    for (int i = 0; i < 4; i++)
#pragma unroll
        for (int j = 0; j < 8; j++) acc[i][j] = 0.f;

    for (int k0 = 0; k0 < CH; k0 += 32) {
        // A tile from g_ao [n][c] layout: c-fast load for coalescing
#pragma unroll
        for (int i = tid; i < 64 * 32; i += 128) {
            int m = i >> 5, kk = i & 31;
            sA[kk][m] = g_ao[((size_t)b * NSP + n0 + m) * CH + k0 + kk];
        }
#pragma unroll
        for (int i = tid; i < 64 * 32; i += 128) {
            int o = i >> 5, kk = i & 31;
            sB[kk][o] = w[(size_t)(o0 + o) * CH + k0 + kk];
        }
        __syncthreads();
#pragma unroll
        for (int kk = 0; kk < 32; kk++) {
            float a[4], bb[8];
#pragma unroll
            for (int i = 0; i < 4; i++) a[i] = sA[kk][mr + i];
#pragma unroll
            for (int j = 0; j < 8; j++) bb[j] = sB[kk][oc + j];
#pragma unroll
            for (int i = 0; i < 4; i++)
#pragma unroll
                for (int j = 0; j < 8; j++) acc[i][j] += a[i] * bb[j];
        }
        __syncthreads();
    }
    // epilogue: transposed write to [B,C,N] + residual. 4 consecutive n per store.
#pragma unroll
    for (int j = 0; j < 8; j++) {
        int o = o0 + oc + j;
        size_t p = ((size_t)(b * CH + o)) * NSP + n0 + mr;
        float bo = bias[o];
        float4 xr = *(const float4*)(x + p);
        float4 w4;
        w4.x = xr.x + acc[0][j] + bo;
        w4.y = xr.y + acc[1][j] + bo;
        w4.z = xr.z + acc[2][j] + bo;
        w4.w = xr.w + acc[3][j] + bo;
        *(float4*)(out + p) = w4;
    }
}

// ================= launch =================
extern "C" void kernel_launch(void* const* d_in, const int* in_sizes, int n_in,
                              void* d_out, int out_size) {
    const float* x      = (const float*)d_in[0];
    const float* gamma  = (const float*)d_in[1];
    const float* beta   = (const float*)d_in[2];
    const float* w_qkv  = (const float*)d_in[3];
    const float* b_qkv  = (const float*)d_in[4];
    const float* w_proj = (const float*)d_in[5];
    const float* b_proj = (const float*)d_in[6];
    float* out = (float*)d_out;

    constexpr size_t ATT_SMEM =
        (size_t)(128 * 64 + 128 * 64 + 64 * 128 + 64 * 65) * sizeof(float); // 114944 B
    cudaFuncSetAttribute(attn_kernel, cudaFuncAttributeMaxDynamicSharedMemorySize,
                         (int)ATT_SMEM);

    gn_stats_kernel<<<NBATCH * NGRP, 256>>>(x);
    qkv_gemm_kernel<<<dim3(256, 6), 128>>>(x, gamma, beta, w_qkv, b_qkv);
    attn_kernel<<<dim3(NSP / 64, NBATCH), 128, ATT_SMEM>>>();
    proj_gemm_kernel<<<dim3(256, 2), 128>>>(x, w_proj, b_proj, out);
}

// round 8
// speedup vs baseline: 9.6669x; 9.6669x over previous
#include <cuda_runtime.h>
#include <cuda_bf16.h>
#include <cstdint>

#define CH     128
#define NGRP   8
#define CPG    16
#define NBATCH 2
#define NSP    8192
#define EPSF   1e-5f
#define QSCALE 0.08838834764831845f   // 1/sqrt(128)
#define BR     64
#define BC     64
#define PITCH  272                    // smem row pitch bytes (256 data + 16 pad)

// ---- scratch (device globals; no allocations allowed) ----
__device__ float g_mean[NBATCH * NGRP];
__device__ float g_rstd[NBATCH * NGRP];
__device__ __nv_bfloat16 g_qh[NBATCH * NSP * CH];   // [B,N,C] pre-scaled
__device__ __nv_bfloat16 g_kh[NBATCH * NSP * CH];   // [B,N,C]
__device__ __nv_bfloat16 g_vh[NBATCH * NSP * CH];   // [B,N,C]
__device__ float g_ao[NBATCH * NSP * CH];           // attention out [B,N,C]

// ======================= PTX helpers (plain sm_80+ ISA) =====================
__device__ __forceinline__ uint32_t smem_to_u32(const void* p) {
    uint32_t a;
    asm("{ .reg .u64 t; cvta.to.shared.u64 t, %1; cvt.u32.u64 %0, t; }"
        : "=r"(a) : "l"(p));
    return a;
}
#define LDSM_X4(r0, r1, r2, r3, addr) \
    asm volatile("ldmatrix.sync.aligned.m8n8.x4.shared.b16 {%0,%1,%2,%3}, [%4];" \
        : "=r"(r0), "=r"(r1), "=r"(r2), "=r"(r3) : "r"(addr))
#define LDSM_X2(r0, r1, addr) \
    asm volatile("ldmatrix.sync.aligned.m8n8.x2.shared.b16 {%0,%1}, [%2];" \
        : "=r"(r0), "=r"(r1) : "r"(addr))
#define LDSM_X2T(r0, r1, addr) \
    asm volatile("ldmatrix.sync.aligned.m8n8.x2.trans.shared.b16 {%0,%1}, [%2];" \
        : "=r"(r0), "=r"(r1) : "r"(addr))
#define CVT_BF16X2(res, lo, hi) \
    asm("cvt.rn.satfinite.bf16x2.f32 %0, %1, %2;" : "=r"(res) : "f"(hi), "f"(lo))

__device__ __forceinline__ void mma16816(float* d, const uint32_t* a,
                                         uint32_t b0, uint32_t b1) {
    asm volatile(
        "mma.sync.aligned.m16n8k16.row.col.f32.bf16.bf16.f32 "
        "{%0,%1,%2,%3}, {%4,%5,%6,%7}, {%8,%9}, {%0,%1,%2,%3};"
        : "+f"(d[0]), "+f"(d[1]), "+f"(d[2]), "+f"(d[3])
        : "r"(a[0]), "r"(a[1]), "r"(a[2]), "r"(a[3]), "r"(b0), "r"(b1));
}

// ================= Kernel 1: GroupNorm statistics =================
__global__ void gn_stats_kernel(const float* __restrict__ x) {
    const int bg = blockIdx.x;
    const int b = bg >> 3, g = bg & 7;
    const float* base = x + ((size_t)b * CH + g * CPG) * NSP;
    const int total = CPG * NSP;
    const int tid = threadIdx.x;
    float s = 0.f, ss = 0.f;
    const float4* p4 = (const float4*)base;
    for (int i = tid; i < total / 4; i += 256) {
        float4 v = p4[i];
        s  += (v.x + v.y) + (v.z + v.w);
        ss += (v.x * v.x + v.y * v.y) + (v.z * v.z + v.w * v.w);
    }
    __shared__ float shs[256], shss[256];
    shs[tid] = s; shss[tid] = ss;
    __syncthreads();
    for (int o = 128; o > 0; o >>= 1) {
        if (tid < o) { shs[tid] += shs[tid + o]; shss[tid] += shss[tid + o]; }
        __syncthreads();
    }
    if (tid == 0) {
        float mean = shs[0] / (float)total;
        float var  = shss[0] / (float)total - mean * mean;
        g_mean[bg] = mean;
        g_rstd[bg] = rsqrtf(var + EPSF);
    }
}

// ============ Kernel 2: fused GN-apply + QKV GEMM -> bf16 q/k/v =============
__global__ __launch_bounds__(128) void qkv_gemm_kernel(
    const float* __restrict__ x, const float* __restrict__ gamma,
    const float* __restrict__ beta, const float* __restrict__ w,
    const float* __restrict__ bias)
{
    __shared__ float sA[32][65];
    __shared__ float sB[32][65];
    const int mblk = blockIdx.x;
    const int b  = mblk >> 7;
    const int n0 = (mblk & 127) << 6;
    const int o0 = blockIdx.y << 6;
    const int tid = threadIdx.x;
    const int ty = tid >> 3, tx = tid & 7;
    const int mr = ty << 2;
    const int oc = tx << 3;
    float acc[4][8];
#pragma unroll
    for (int i = 0; i < 4; i++)
#pragma unroll
        for (int j = 0; j < 8; j++) acc[i][j] = 0.f;

    for (int k0 = 0; k0 < CH; k0 += 32) {
#pragma unroll
        for (int i = tid; i < 32 * 64; i += 128) {
            int kk = i >> 6, m = i & 63;
            int c = k0 + kk;
            int bg = (b << 3) + (c >> 4);
            float xv = x[((size_t)b * CH + c) * NSP + n0 + m];
            sA[kk][m] = (xv - g_mean[bg]) * g_rstd[bg] * gamma[c] + beta[c];
        }
#pragma unroll
        for (int i = tid; i < 64 * 32; i += 128) {
            int o = i >> 5, kk = i & 31;
            sB[kk][o] = w[(size_t)(o0 + o) * CH + k0 + kk];
        }
        __syncthreads();
#pragma unroll
        for (int kk = 0; kk < 32; kk++) {
            float a[4], bb[8];
#pragma unroll
            for (int i = 0; i < 4; i++) a[i] = sA[kk][mr + i];
#pragma unroll
            for (int j = 0; j < 8; j++) bb[j] = sB[kk][oc + j];
#pragma unroll
            for (int i = 0; i < 4; i++)
#pragma unroll
                for (int j = 0; j < 8; j++) acc[i][j] += a[i] * bb[j];
        }
        __syncthreads();
    }
    const int og = o0 + oc;
    __nv_bfloat16* dst;
    float scale = 1.f;
    int ob;
    if (og < CH)            { dst = g_qh; ob = og;          scale = QSCALE; }
    else if (og < 2 * CH)   { dst = g_kh; ob = og - CH; }
    else                    { dst = g_vh; ob = og - 2 * CH; }
#pragma unroll
    for (int i = 0; i < 4; i++) {
        size_t row = ((size_t)b * NSP + n0 + mr + i) * CH;
#pragma unroll
        for (int j = 0; j < 8; j++)
            dst[row + ob + j] = __float2bfloat16((acc[i][j] + bias[og + j]) * scale);
    }
}

// ========== Kernel 3: mma.sync bf16 flash attention (no-rescale) ============
// 4 warps, Br=64 (16 rows/warp), Bc=64 keys/tile, 128 tiles.
// S,P stay in registers (FA2 accumulator->A-operand reuse). Unnormalized exp,
// row-sum l accumulated, single divide at the end.
#define ATT_SMEM2 (3 * BR * PITCH)   // Q,K,V tiles: 52224 B

__global__ __launch_bounds__(128) void attn_mma_kernel() {
    extern __shared__ char smc[];
    const uint32_t sQ = smem_to_u32(smc);
    const uint32_t sK = sQ + BR * PITCH;
    const uint32_t sV = sK + BC * PITCH;
    const int tid = threadIdx.x;
    const int w = tid >> 5, lane = tid & 31;
    const int b = blockIdx.y;
    const int n0 = blockIdx.x * BR;
    const int q0 = w * 16;
    const int tq = lane >> 2;   // accum row within m16
    const int tc = lane & 3;    // accum col pair

    // ---- load Q tile (64 x 128 bf16, padded rows) ----
    const __nv_bfloat16* qg = g_qh + ((size_t)b * NSP + n0) * CH;
    for (int i = tid; i < BR * 16; i += 128) {
        int r = i >> 4, c = i & 15;
        *(uint4*)(smc + r * PITCH + c * 16) =
            *(const uint4*)((const char*)qg + r * 256 + c * 16);
    }
    __syncthreads();

    // ---- preload all Q A-fragments: 8 k-steps x 4 regs ----
    uint32_t qa[8][4];
#pragma unroll
    for (int ks = 0; ks < 8; ks++) {
        uint32_t addr = sQ + (q0 + (lane & 15)) * PITCH
                      + (ks * 16 + ((lane >> 4) << 3)) * 2;
        LDSM_X4(qa[ks][0], qa[ks][1], qa[ks][2], qa[ks][3], addr);
    }

    float o[16][4];
#pragma unroll
    for (int i = 0; i < 16; i++)
#pragma unroll
        for (int j = 0; j < 4; j++) o[i][j] = 0.f;
    float l0 = 0.f, l1 = 0.f;

    for (int t = 0; t < NSP / BC; t++) {
        __syncthreads();   // prior iteration done reading sK/sV
        const char* kg = (const char*)(g_kh + ((size_t)b * NSP + (size_t)t * BC) * CH);
        const char* vg = (const char*)(g_vh + ((size_t)b * NSP + (size_t)t * BC) * CH);
        for (int i = tid; i < BC * 16; i += 128) {
            int r = i >> 4, c = i & 15;
            *(uint4*)(smc + (BR * PITCH) + r * PITCH + c * 16) =
                *(const uint4*)(kg + r * 256 + c * 16);
            *(uint4*)(smc + (2 * BR * PITCH) + r * PITCH + c * 16) =
                *(const uint4*)(vg + r * 256 + c * 16);
        }
        __syncthreads();

        // ---- S = Q @ K^T  (8 n-tiles of 8 tokens) ----
        float s[8][4];
#pragma unroll
        for (int i = 0; i < 8; i++)
#pragma unroll
            for (int j = 0; j < 4; j++) s[i][j] = 0.f;
#pragma unroll
        for (int ks = 0; ks < 8; ks++) {
#pragma unroll
            for (int nt = 0; nt < 8; nt++) {
                uint32_t b0, b1;
                uint32_t addr = sK + (nt * 8 + (lane & 7)) * PITCH
                              + (ks * 16 + ((lane >> 3) & 1) * 8) * 2;
                LDSM_X2(b0, b1, addr);
                mma16816(s[nt], qa[ks], b0, b1);
            }
        }

        // ---- p = exp(S); pack to bf16 A-fragments; accumulate row sums ----
        uint32_t pa[4][4];
#pragma unroll
        for (int kt = 0; kt < 4; kt++) {
            float e00 = __expf(s[2 * kt][0]),     e01 = __expf(s[2 * kt][1]);
            float e02 = __expf(s[2 * kt][2]),     e03 = __expf(s[2 * kt][3]);
            float e10 = __expf(s[2 * kt + 1][0]), e11 = __expf(s[2 * kt + 1][1]);
            float e12 = __expf(s[2 * kt + 1][2]), e13 = __expf(s[2 * kt + 1][3]);
            l0 += (e00 + e01) + (e10 + e11);
            l1 += (e02 + e03) + (e12 + e13);
            CVT_BF16X2(pa[kt][0], e00, e01);
            CVT_BF16X2(pa[kt][1], e02, e03);
            CVT_BF16X2(pa[kt][2], e10, e11);
            CVT_BF16X2(pa[kt][3], e12, e13);
        }

        // ---- O += P @ V  (16 channel n-tiles, 4 k-steps of 16 tokens) ----
#pragma unroll
        for (int ct = 0; ct < 16; ct++) {
#pragma unroll
            for (int kt = 0; kt < 4; kt++) {
                uint32_t b0, b1;
                uint32_t addr = sV + (kt * 16 + (lane & 15)) * PITCH + ct * 16;
                LDSM_X2T(b0, b1, addr);
                mma16816(o[ct], pa[kt], b0, b1);
            }
        }
    }

    // ---- finalize: reduce l over quad, divide, store ----
    l0 += __shfl_xor_sync(0xffffffffu, l0, 1);
    l0 += __shfl_xor_sync(0xffffffffu, l0, 2);
    l1 += __shfl_xor_sync(0xffffffffu, l1, 1);
    l1 += __shfl_xor_sync(0xffffffffu, l1, 2);
    const float i0 = 1.f / l0, i1 = 1.f / l1;
    float* ob = g_ao + ((size_t)b * NSP + n0 + q0) * CH;
#pragma unroll
    for (int ct = 0; ct < 16; ct++) {
        int col = ct * 8 + tc * 2;
        float2 r0 = make_float2(o[ct][0] * i0, o[ct][1] * i0);
        float2 r1 = make_float2(o[ct][2] * i1, o[ct][3] * i1);
        *(float2*)(ob + (size_t)tq * CH + col)       = r0;
        *(float2*)(ob + (size_t)(tq + 8) * CH + col) = r1;
    }
}

// ================= Kernel 4: proj GEMM + bias + residual =================
__global__ __launch_bounds__(128) void proj_gemm_kernel(
    const float* __restrict__ x, const float* __restrict__ w,
    const float* __restrict__ bias, float* __restrict__ out)
{
    __shared__ float sA[32][65];
    __shared__ float sB[32][65];
    const int mblk = blockIdx.x;
    const int b  = mblk >> 7;
    const int n0 = (mblk & 127) << 6;
    const int o0 = blockIdx.y << 6;
    const int tid = threadIdx.x;
    const int ty = tid >> 3, tx = tid & 7;
    const int mr = ty << 2;
    const int oc = tx << 3;
    float acc[4][8];
#pragma unroll
    for (int i = 0; i < 4; i++)
#pragma unroll
        for (int j = 0; j < 8; j++) acc[i][j] = 0.f;

    for (int k0 = 0; k0 < CH; k0 += 32) {
#pragma unroll
        for (int i = tid; i < 64 * 32; i += 128) {
            int m = i >> 5, kk = i & 31;
            sA[kk][m] = g_ao[((size_t)b * NSP + n0 + m) * CH + k0 + kk];
        }
#pragma unroll
        for (int i = tid; i < 64 * 32; i += 128) {
            int o = i >> 5, kk = i & 31;
            sB[kk][o] = w[(size_t)(o0 + o) * CH + k0 + kk];
        }
        __syncthreads();
#pragma unroll
        for (int kk = 0; kk < 32; kk++) {
            float a[4], bb[8];
#pragma unroll
            for (int i = 0; i < 4; i++) a[i] = sA[kk][mr + i];
#pragma unroll
            for (int j = 0; j < 8; j++) bb[j] = sB[kk][oc + j];
#pragma unroll
            for (int i = 0; i < 4; i++)
#pragma unroll
                for (int j = 0; j < 8; j++) acc[i][j] += a[i] * bb[j];
        }
        __syncthreads();
    }
#pragma unroll
    for (int j = 0; j < 8; j++) {
        int o = o0 + oc + j;
        size_t p = ((size_t)(b * CH + o)) * NSP + n0 + mr;
        float bo = bias[o];
        float4 xr = *(const float4*)(x + p);
        float4 w4;
        w4.x = xr.x + acc[0][j] + bo;
        w4.y = xr.y + acc[1][j] + bo;
        w4.z = xr.z + acc[2][j] + bo;
        w4.w = xr.w + acc[3][j] + bo;
        *(float4*)(out + p) = w4;
    }
}

// ================= launch =================
extern "C" void kernel_launch(void* const* d_in, const int* in_sizes, int n_in,
                              void* d_out, int out_size) {
    const float* x      = (const float*)d_in[0];
    const float* gamma  = (const float*)d_in[1];
    const float* beta   = (const float*)d_in[2];
    const float* w_qkv  = (const float*)d_in[3];
    const float* b_qkv  = (const float*)d_in[4];
    const float* w_proj = (const float*)d_in[5];
    const float* b_proj = (const float*)d_in[6];
    float* out = (float*)d_out;

    cudaFuncSetAttribute(attn_mma_kernel, cudaFuncAttributeMaxDynamicSharedMemorySize,
                         ATT_SMEM2);

    gn_stats_kernel<<<NBATCH * NGRP, 256>>>(x);
    qkv_gemm_kernel<<<dim3(256, 6), 128>>>(x, gamma, beta, w_qkv, b_qkv);
    attn_mma_kernel<<<dim3(NSP / BR, NBATCH), 128, ATT_SMEM2>>>();
    proj_gemm_kernel<<<dim3(256, 2), 128>>>(x, w_proj, b_proj, out);
}

// round 12
// speedup vs baseline: 11.7282x; 1.2132x over previous
#include <cuda_runtime.h>
#include <cuda_bf16.h>
#include <cstdint>

#define CH     128
#define NGRP   8
#define CPG    16
#define NBATCH 2
#define NSP    8192
#define EPSF   1e-5f
#define QSCALE 0.08838834764831845f   // 1/sqrt(128)
#define BR     64
#define BC     64
#define PITCH  272                    // smem row pitch bytes (256 data + 16 pad)
#define NTILE  (NSP / BC)             // 128

// ---- scratch (device globals; no allocations allowed) ----
__device__ float g_mean[NBATCH * NGRP];
__device__ float g_rstd[NBATCH * NGRP];
__device__ __nv_bfloat16 g_qh[NBATCH * NSP * CH];   // [B,N,C] pre-scaled
__device__ __nv_bfloat16 g_kh[NBATCH * NSP * CH];   // [B,N,C]
__device__ __nv_bfloat16 g_vh[NBATCH * NSP * CH];   // [B,N,C]
__device__ float g_ao[NBATCH * NSP * CH];           // attention out [B,N,C]

// ======================= PTX helpers (plain sm_80+ ISA) =====================
__device__ __forceinline__ uint32_t smem_to_u32(const void* p) {
    uint32_t a;
    asm("{ .reg .u64 t; cvta.to.shared.u64 t, %1; cvt.u32.u64 %0, t; }"
        : "=r"(a) : "l"(p));
    return a;
}
#define LDSM_X4(r0, r1, r2, r3, addr) \
    asm volatile("ldmatrix.sync.aligned.m8n8.x4.shared.b16 {%0,%1,%2,%3}, [%4];" \
        : "=r"(r0), "=r"(r1), "=r"(r2), "=r"(r3) : "r"(addr))
#define LDSM_X4T(r0, r1, r2, r3, addr) \
    asm volatile("ldmatrix.sync.aligned.m8n8.x4.trans.shared.b16 {%0,%1,%2,%3}, [%4];" \
        : "=r"(r0), "=r"(r1), "=r"(r2), "=r"(r3) : "r"(addr))
#define CVT_BF16X2(res, lo, hi) \
    asm("cvt.rn.satfinite.bf16x2.f32 %0, %1, %2;" : "=r"(res) : "f"(hi), "f"(lo))
#define CP_ASYNC16(dst, src) \
    asm volatile("cp.async.cg.shared.global [%0], [%1], 16;" \
        :: "r"(dst), "l"(src) : "memory")
#define CP_COMMIT()  asm volatile("cp.async.commit_group;" ::: "memory")
#define CP_WAIT0()   asm volatile("cp.async.wait_group 0;" ::: "memory")

__device__ __forceinline__ void mma16816(float* d, const uint32_t* a,
                                         uint32_t b0, uint32_t b1) {
    asm volatile(
        "mma.sync.aligned.m16n8k16.row.col.f32.bf16.bf16.f32 "
        "{%0,%1,%2,%3}, {%4,%5,%6,%7}, {%8,%9}, {%0,%1,%2,%3};"
        : "+f"(d[0]), "+f"(d[1]), "+f"(d[2]), "+f"(d[3])
        : "r"(a[0]), "r"(a[1]), "r"(a[2]), "r"(a[3]), "r"(b0), "r"(b1));
}

// ================= Kernel 1: GroupNorm statistics =================
__global__ void gn_stats_kernel(const float* __restrict__ x) {
    const int bg = blockIdx.x;
    const int b = bg >> 3, g = bg & 7;
    const float* base = x + ((size_t)b * CH + g * CPG) * NSP;
    const int total = CPG * NSP;
    const int tid = threadIdx.x;
    float s = 0.f, ss = 0.f;
    const float4* p4 = (const float4*)base;
    for (int i = tid; i < total / 4; i += 256) {
        float4 v = p4[i];
        s  += (v.x + v.y) + (v.z + v.w);
        ss += (v.x * v.x + v.y * v.y) + (v.z * v.z + v.w * v.w);
    }
    __shared__ float shs[256], shss[256];
    shs[tid] = s; shss[tid] = ss;
    __syncthreads();
    for (int o = 128; o > 0; o >>= 1) {
        if (tid < o) { shs[tid] += shs[tid + o]; shss[tid] += shss[tid + o]; }
        __syncthreads();
    }
    if (tid == 0) {
        float mean = shs[0] / (float)total;
        float var  = shss[0] / (float)total - mean * mean;
        g_mean[bg] = mean;
        g_rstd[bg] = rsqrtf(var + EPSF);
    }
}

// ============ Kernel 2: fused GN-apply + QKV GEMM -> bf16 q/k/v =============
__global__ __launch_bounds__(128) void qkv_gemm_kernel(
    const float* __restrict__ x, const float* __restrict__ gamma,
    const float* __restrict__ beta, const float* __restrict__ w,
    const float* __restrict__ bias)
{
    __shared__ float sA[32][65];
    __shared__ float sB[32][65];
    const int mblk = blockIdx.x;
    const int b  = mblk >> 7;
    const int n0 = (mblk & 127) << 6;
    const int o0 = blockIdx.y << 6;
    const int tid = threadIdx.x;
    const int ty = tid >> 3, tx = tid & 7;
    const int mr = ty << 2;
    const int oc = tx << 3;
    float acc[4][8];
#pragma unroll
    for (int i = 0; i < 4; i++)
#pragma unroll
        for (int j = 0; j < 8; j++) acc[i][j] = 0.f;

    for (int k0 = 0; k0 < CH; k0 += 32) {
#pragma unroll
        for (int i = tid; i < 32 * 64; i += 128) {
            int kk = i >> 6, m = i & 63;
            int c = k0 + kk;
            int bg = (b << 3) + (c >> 4);
            float xv = x[((size_t)b * CH + c) * NSP + n0 + m];
            sA[kk][m] = (xv - g_mean[bg]) * g_rstd[bg] * gamma[c] + beta[c];
        }
#pragma unroll
        for (int i = tid; i < 64 * 32; i += 128) {
            int o = i >> 5, kk = i & 31;
            sB[kk][o] = w[(size_t)(o0 + o) * CH + k0 + kk];
        }
        __syncthreads();
#pragma unroll
        for (int kk = 0; kk < 32; kk++) {
            float a[4], bb[8];
#pragma unroll
            for (int i = 0; i < 4; i++) a[i] = sA[kk][mr + i];
#pragma unroll
            for (int j = 0; j < 8; j++) bb[j] = sB[kk][oc + j];
#pragma unroll
            for (int i = 0; i < 4; i++)
#pragma unroll
                for (int j = 0; j < 8; j++) acc[i][j] += a[i] * bb[j];
        }
        __syncthreads();
    }
    const int og = o0 + oc;
    __nv_bfloat16* dst;
    float scale = 1.f;
    int ob;
    if (og < CH)            { dst = g_qh; ob = og;          scale = QSCALE; }
    else if (og < 2 * CH)   { dst = g_kh; ob = og - CH; }
    else                    { dst = g_vh; ob = og - 2 * CH; }
#pragma unroll
    for (int i = 0; i < 4; i++) {
        size_t row = ((size_t)b * NSP + n0 + mr + i) * CH;
#pragma unroll
        for (int j = 0; j < 8; j++)
            dst[row + ob + j] = __float2bfloat16((acc[i][j] + bias[og + j]) * scale);
    }
}

// ========== Kernel 3: mma.sync bf16 flash attention (no-rescale) ============
// 4 warps, Br=64 (16 rows/warp), Bc=64 keys/tile, 128 tiles.
// cp.async double-buffered K/V, x4 ldmatrix, one barrier per tile.
// smem: Q tile + 2x (K,V) buffers, PITCH-padded rows.
#define QBYTES   (BR * PITCH)
#define KVBYTES  (2 * BC * PITCH)      // one K+V buffer pair
#define ATT_SMEM3 (QBYTES + 2 * KVBYTES)   // 87040 B

__global__ __launch_bounds__(128) void attn_mma_kernel() {
    extern __shared__ char smc[];
    const uint32_t sQ = smem_to_u32(smc);
    const int tid = threadIdx.x;
    const int w = tid >> 5, lane = tid & 31;
    const int b = blockIdx.y;
    const int n0 = blockIdx.x * BR;
    const int q0 = w * 16;
    const int tq = lane >> 2;   // accum row within m16
    const int tc = lane & 3;    // accum col pair

    const int lr = tid >> 4;        // cp.async row (0..7)
    const int lc = tid & 15;        // cp.async col (0..15)
    const uint32_t cpoff = (uint32_t)lr * PITCH + lc * 16;
    const size_t   goff  = (size_t)lr * 256 + lc * 16;

    // ---- prologue: cp.async Q tile + K/V tile 0 ----
    const char* qg = (const char*)(g_qh + ((size_t)b * NSP + n0) * CH);
#pragma unroll
    for (int r8 = 0; r8 < 8; r8++)
        CP_ASYNC16(sQ + r8 * 8 * PITCH + cpoff, qg + r8 * 8 * 256 + goff);
    {
        const char* kg = (const char*)(g_kh + (size_t)b * NSP * CH);
        const char* vg = (const char*)(g_vh + (size_t)b * NSP * CH);
        uint32_t kb = sQ + QBYTES, vb = kb + BC * PITCH;
#pragma unroll
        for (int r8 = 0; r8 < 8; r8++) {
            CP_ASYNC16(kb + r8 * 8 * PITCH + cpoff, kg + r8 * 8 * 256 + goff);
            CP_ASYNC16(vb + r8 * 8 * PITCH + cpoff, vg + r8 * 8 * 256 + goff);
        }
    }
    CP_COMMIT();
    CP_WAIT0();
    __syncthreads();

    // ---- preload all Q A-fragments: 8 k-steps x 4 regs ----
    uint32_t qa[8][4];
#pragma unroll
    for (int ks = 0; ks < 8; ks++) {
        uint32_t addr = sQ + (q0 + (lane & 15)) * PITCH
                      + (ks * 16 + ((lane >> 4) << 3)) * 2;
        LDSM_X4(qa[ks][0], qa[ks][1], qa[ks][2], qa[ks][3], addr);
    }

    float o[16][4];
#pragma unroll
    for (int i = 0; i < 16; i++)
#pragma unroll
        for (int j = 0; j < 4; j++) o[i][j] = 0.f;
    float l0 = 0.f, l1 = 0.f;

    // ldmatrix lane-address components (constant across tiles)
    const uint32_t kRowSel = (((lane >> 4) << 3) + (lane & 7));            // QK x4
    const uint32_t kColSel = (((lane >> 3) & 1) << 3);
    const uint32_t vRowSel = ((((lane >> 3) & 1) << 3) + (lane & 7));      // PV x4T
    const uint32_t vColSel = ((lane >> 4) << 4);

    for (int t = 0; t < NTILE; t++) {
        const uint32_t cur = (uint32_t)(t & 1);
        const uint32_t sK = sQ + QBYTES + cur * KVBYTES;
        const uint32_t sV = sK + BC * PITCH;

        // ---- issue next tile's K/V into the other buffer ----
        if (t + 1 < NTILE) {
            const char* kg = (const char*)(g_kh + ((size_t)b * NSP + (size_t)(t + 1) * BC) * CH);
            const char* vg = (const char*)(g_vh + ((size_t)b * NSP + (size_t)(t + 1) * BC) * CH);
            uint32_t kb = sQ + QBYTES + (cur ^ 1u) * KVBYTES;
            uint32_t vb = kb + BC * PITCH;
#pragma unroll
            for (int r8 = 0; r8 < 8; r8++) {
                CP_ASYNC16(kb + r8 * 8 * PITCH + cpoff, kg + r8 * 8 * 256 + goff);
                CP_ASYNC16(vb + r8 * 8 * PITCH + cpoff, vg + r8 * 8 * 256 + goff);
            }
        }
        CP_COMMIT();

        // ---- S = Q @ K^T  (4 x4-LDSM feed 8 n-tiles) ----
        float s[8][4];
#pragma unroll
        for (int i = 0; i < 8; i++)
#pragma unroll
            for (int j = 0; j < 4; j++) s[i][j] = 0.f;
#pragma unroll
        for (int ks = 0; ks < 8; ks++) {
            const uint32_t colb = (ks * 16 + kColSel) * 2;
#pragma unroll
            for (int nt2 = 0; nt2 < 4; nt2++) {
                uint32_t b0, b1, b2, b3;
                uint32_t addr = sK + (nt2 * 16 + kRowSel) * PITCH + colb;
                LDSM_X4(b0, b1, b2, b3, addr);
                mma16816(s[2 * nt2],     qa[ks], b0, b1);
                mma16816(s[2 * nt2 + 1], qa[ks], b2, b3);
            }
        }

        // ---- p = exp(S); pack to bf16 A-fragments; accumulate row sums ----
        uint32_t pa[4][4];
#pragma unroll
        for (int kt = 0; kt < 4; kt++) {
            float e00 = __expf(s[2 * kt][0]),     e01 = __expf(s[2 * kt][1]);
            float e02 = __expf(s[2 * kt][2]),     e03 = __expf(s[2 * kt][3]);
            float e10 = __expf(s[2 * kt + 1][0]), e11 = __expf(s[2 * kt + 1][1]);
            float e12 = __expf(s[2 * kt + 1][2]), e13 = __expf(s[2 * kt + 1][3]);
            l0 += (e00 + e01) + (e10 + e11);
            l1 += (e02 + e03) + (e12 + e13);
            CVT_BF16X2(pa[kt][0], e00, e01);
            CVT_BF16X2(pa[kt][1], e02, e03);
            CVT_BF16X2(pa[kt][2], e10, e11);
            CVT_BF16X2(pa[kt][3], e12, e13);
        }

        // ---- O += P @ V  (x4T LDSM feeds 2 channel-tiles) ----
#pragma unroll
        for (int ct2 = 0; ct2 < 8; ct2++) {
            const uint32_t colb = ct2 * 32 + vColSel;
#pragma unroll
            for (int kt = 0; kt < 4; kt++) {
                uint32_t b0, b1, b2, b3;
                uint32_t addr = sV + (kt * 16 + vRowSel) * PITCH + colb;
                LDSM_X4T(b0, b1, b2, b3, addr);
                mma16816(o[2 * ct2],     pa[kt], b0, b1);
                mma16816(o[2 * ct2 + 1], pa[kt], b2, b3);
            }
        }

        CP_WAIT0();
        __syncthreads();   // next buffer ready; this buffer free for overwrite
    }

    // ---- finalize: reduce l over quad, divide, store ----
    l0 += __shfl_xor_sync(0xffffffffu, l0, 1);
    l0 += __shfl_xor_sync(0xffffffffu, l0, 2);
    l1 += __shfl_xor_sync(0xffffffffu, l1, 1);
    l1 += __shfl_xor_sync(0xffffffffu, l1, 2);
    const float i0 = 1.f / l0, i1 = 1.f / l1;
    float* ob = g_ao + ((size_t)b * NSP + n0 + q0) * CH;
#pragma unroll
    for (int ct = 0; ct < 16; ct++) {
        int col = ct * 8 + tc * 2;
        float2 r0 = make_float2(o[ct][0] * i0, o[ct][1] * i0);
        float2 r1 = make_float2(o[ct][2] * i1, o[ct][3] * i1);
        *(float2*)(ob + (size_t)tq * CH + col)       = r0;
        *(float2*)(ob + (size_t)(tq + 8) * CH + col) = r1;
    }
}

// ================= Kernel 4: proj GEMM + bias + residual =================
__global__ __launch_bounds__(128) void proj_gemm_kernel(
    const float* __restrict__ x, const float* __restrict__ w,
    const float* __restrict__ bias, float* __restrict__ out)
{
    __shared__ float sA[32][65];
    __shared__ float sB[32][65];
    const int mblk = blockIdx.x;
    const int b  = mblk >> 7;
    const int n0 = (mblk & 127) << 6;
    const int o0 = blockIdx.y << 6;
    const int tid = threadIdx.x;
    const int ty = tid >> 3, tx = tid & 7;
    const int mr = ty << 2;
    const int oc = tx << 3;
    float acc[4][8];
#pragma unroll
    for (int i = 0; i < 4; i++)
#pragma unroll
        for (int j = 0; j < 8; j++) acc[i][j] = 0.f;

    for (int k0 = 0; k0 < CH; k0 += 32) {
#pragma unroll
        for (int i = tid; i < 64 * 32; i += 128) {
            int m = i >> 5, kk = i & 31;
            sA[kk][m] = g_ao[((size_t)b * NSP + n0 + m) * CH + k0 + kk];
        }
#pragma unroll
        for (int i = tid; i < 64 * 32; i += 128) {
            int o = i >> 5, kk = i & 31;
            sB[kk][o] = w[(size_t)(o0 + o) * CH + k0 + kk];
        }
        __syncthreads();
#pragma unroll
        for (int kk = 0; kk < 32; kk++) {
            float a[4], bb[8];
#pragma unroll
            for (int i = 0; i < 4; i++) a[i] = sA[kk][mr + i];
#pragma unroll
            for (int j = 0; j < 8; j++) bb[j] = sB[kk][oc + j];
#pragma unroll
            for (int i = 0; i < 4; i++)
#pragma unroll
                for (int j = 0; j < 8; j++) acc[i][j] += a[i] * bb[j];
        }
        __syncthreads();
    }
#pragma unroll
    for (int j = 0; j < 8; j++) {
        int o = o0 + oc + j;
        size_t p = ((size_t)(b * CH + o)) * NSP + n0 + mr;
        float bo = bias[o];
        float4 xr = *(const float4*)(x + p);
        float4 w4;
        w4.x = xr.x + acc[0][j] + bo;
        w4.y = xr.y + acc[1][j] + bo;
        w4.z = xr.z + acc[2][j] + bo;
        w4.w = xr.w + acc[3][j] + bo;
        *(float4*)(out + p) = w4;
    }
}

// ================= launch =================
extern "C" void kernel_launch(void* const* d_in, const int* in_sizes, int n_in,
                              void* d_out, int out_size) {
    const float* x      = (const float*)d_in[0];
    const float* gamma  = (const float*)d_in[1];
    const float* beta   = (const float*)d_in[2];
    const float* w_qkv  = (const float*)d_in[3];
    const float* b_qkv  = (const float*)d_in[4];
    const float* w_proj = (const float*)d_in[5];
    const float* b_proj = (const float*)d_in[6];
    float* out = (float*)d_out;

    cudaFuncSetAttribute(attn_mma_kernel, cudaFuncAttributeMaxDynamicSharedMemorySize,
                         ATT_SMEM3);

    gn_stats_kernel<<<NBATCH * NGRP, 256>>>(x);
    qkv_gemm_kernel<<<dim3(256, 6), 128>>>(x, gamma, beta, w_qkv, b_qkv);
    attn_mma_kernel<<<dim3(NSP / BR, NBATCH), 128, ATT_SMEM3>>>();
    proj_gemm_kernel<<<dim3(256, 2), 128>>>(x, w_proj, b_proj, out);
}